// round 5
// baseline (speedup 1.0000x reference)
#include <cuda_runtime.h>
#include <cstdint>

#define Bb 2
#define Nn 2048
#define Mm 64
#define Ff 128
#define H1 64
#define H2 64
#define TILE 16         // atoms per MLP block
#define MLP_THREADS 512 // 8 pairs x 64 neurons
#define FBLK 192        // force threads per half-atom block

// scratch (allocation-free rule: __device__ globals; zero-initialized)
__device__ float g_buf[Bb * Nn * Ff];   // input-gradient per atom  [B*N, F]
__device__ float Ei_buf[Bb * Nn];       // per-atom energy
__device__ float g_zero[Ff];            // stays all-zero (pad-neighbor source)

__device__ __forceinline__ float sigmoidf(float z) {
    return 1.f / (1.f + __expf(-z));
}

__device__ __forceinline__ void cp_async16(void* dst_smem, const void* src_gmem) {
    unsigned int d = (unsigned int)__cvta_generic_to_shared(dst_smem);
    asm volatile("cp.async.ca.shared.global [%0], [%1], 16;" :: "r"(d), "l"(src_gmem));
}

// ---------------------------------------------------------------------------
// Kernel 1: batched per-atom MLP forward + analytic input gradient.
// 512 threads / 16 atoms; 2 atoms per thread. Activations read as float4
// LDS.128 broadcasts; weights in padded-transposed smem (stride 65).
// ---------------------------------------------------------------------------
__global__ __launch_bounds__(MLP_THREADS) void mlp_kernel(
    const float* __restrict__ image,
    const float* __restrict__ W0,     // [H1, F]   row-major
    const float* __restrict__ W1,     // [H2, H1]  row-major
    const float* __restrict__ Wout)   // [1, H2]
{
    extern __shared__ float sm[];
    float* W0T   = sm;                      // [F][65]:  W0T[f*65+n] = W0[n][f]
    float* W1T   = W0T + Ff * 65;           // [H1][65]: W1T[k*65+j] = W1[j][k]
    float* WoS   = W1T + H1 * 65;           // [64]
    float* xs    = WoS + 64;                // [TILE][128]   (16B aligned)
    float* h0s   = xs  + TILE * Ff;         // [TILE][64]
    float* t1s   = h0s + TILE * H1;         // [TILE][64]
    float* t0s   = t1s + TILE * H2;         // [TILE][64]
    float* ePart = t0s + TILE * H1;         // [TILE][2]

    const int t    = threadIdx.x;
    const int base = blockIdx.x * TILE;
    const int p    = t >> 6;                // pair 0..7
    const int n    = t & 63;                // neuron 0..63
    const int a0   = 2 * p, a1 = 2 * p + 1;

    // ---- stage weights + inputs (coalesced) ----
    for (int i = t; i < H1 * Ff; i += MLP_THREADS) {
        int r = i >> 7, f = i & 127;
        W0T[f * 65 + r] = W0[i];
    }
    for (int i = t; i < H2 * H1; i += MLP_THREADS) {
        int j = i >> 6, k = i & 63;
        W1T[k * 65 + j] = W1[i];
    }
    if (t < H2) WoS[t] = Wout[t];
    for (int i = t; i < TILE * Ff; i += MLP_THREADS)
        xs[i] = image[(size_t)base * Ff + i];
    __syncthreads();

    // ---- phase 1: h0 = sigmoid(x @ W0^T) ----
    {
        const float4* X0 = (const float4*)(xs + a0 * Ff);
        const float4* X1 = (const float4*)(xs + a1 * Ff);
        float s0a = 0.f, s0b = 0.f, s1a = 0.f, s1b = 0.f;
#pragma unroll
        for (int f4 = 0; f4 < Ff / 4; f4++) {
            float4 xa = X0[f4];
            float4 xb = X1[f4];
            const int f = f4 * 4;
            float w0 = W0T[(f + 0) * 65 + n];
            float w1 = W0T[(f + 1) * 65 + n];
            float w2 = W0T[(f + 2) * 65 + n];
            float w3 = W0T[(f + 3) * 65 + n];
            s0a = fmaf(xa.x, w0, s0a); s0b = fmaf(xa.y, w1, s0b);
            s0a = fmaf(xa.z, w2, s0a); s0b = fmaf(xa.w, w3, s0b);
            s1a = fmaf(xb.x, w0, s1a); s1b = fmaf(xb.y, w1, s1b);
            s1a = fmaf(xb.z, w2, s1a); s1b = fmaf(xb.w, w3, s1b);
        }
        h0s[a0 * 64 + n] = sigmoidf(s0a + s0b);
        h0s[a1 * 64 + n] = sigmoidf(s1a + s1b);
    }
    __syncthreads();

    // ---- phase 2: h1, t1 = h1(1-h1)*Wout, Ei partials ----
    {
        const float4* Ha = (const float4*)(h0s + a0 * 64);
        const float4* Hb = (const float4*)(h0s + a1 * 64);
        float s0a = 0.f, s0b = 0.f, s1a = 0.f, s1b = 0.f;
#pragma unroll
        for (int k4 = 0; k4 < H1 / 4; k4++) {
            float4 ha = Ha[k4];
            float4 hb = Hb[k4];
            const int k = k4 * 4;
            float w0 = W1T[(k + 0) * 65 + n];
            float w1 = W1T[(k + 1) * 65 + n];
            float w2 = W1T[(k + 2) * 65 + n];
            float w3 = W1T[(k + 3) * 65 + n];
            s0a = fmaf(ha.x, w0, s0a); s0b = fmaf(ha.y, w1, s0b);
            s0a = fmaf(ha.z, w2, s0a); s0b = fmaf(ha.w, w3, s0b);
            s1a = fmaf(hb.x, w0, s1a); s1b = fmaf(hb.y, w1, s1b);
            s1a = fmaf(hb.z, w2, s1a); s1b = fmaf(hb.w, w3, s1b);
        }
        float wo   = WoS[n];
        float h1_0 = sigmoidf(s0a + s0b);
        float h1_1 = sigmoidf(s1a + s1b);
        t1s[a0 * 64 + n] = h1_0 * (1.f - h1_0) * wo;
        t1s[a1 * 64 + n] = h1_1 * (1.f - h1_1) * wo;
        float e0 = h1_0 * wo, e1 = h1_1 * wo;
#pragma unroll
        for (int off = 16; off > 0; off >>= 1) {
            e0 += __shfl_down_sync(0xffffffffu, e0, off);
            e1 += __shfl_down_sync(0xffffffffu, e1, off);
        }
        if ((n & 31) == 0) {
            int half = n >> 5;
            ePart[a0 * 2 + half] = e0;
            ePart[a1 * 2 + half] = e1;
        }
    }
    __syncthreads();

    // ---- phase 3: g1 = t1 @ W1 ; t0 = h0(1-h0)*g1 ----
    {
        const float4* Ta = (const float4*)(t1s + a0 * 64);
        const float4* Tb = (const float4*)(t1s + a1 * 64);
        float s0a = 0.f, s0b = 0.f, s1a = 0.f, s1b = 0.f;
#pragma unroll
        for (int j4 = 0; j4 < H2 / 4; j4++) {
            float4 ta = Ta[j4];
            float4 tb = Tb[j4];
            const int j = j4 * 4;
            float w0 = W1T[n * 65 + j + 0];   // = W1[j][n]
            float w1 = W1T[n * 65 + j + 1];
            float w2 = W1T[n * 65 + j + 2];
            float w3 = W1T[n * 65 + j + 3];
            s0a = fmaf(ta.x, w0, s0a); s0b = fmaf(ta.y, w1, s0b);
            s0a = fmaf(ta.z, w2, s0a); s0b = fmaf(ta.w, w3, s0b);
            s1a = fmaf(tb.x, w0, s1a); s1b = fmaf(tb.y, w1, s1b);
            s1a = fmaf(tb.z, w2, s1a); s1b = fmaf(tb.w, w3, s1b);
        }
        float h00 = h0s[a0 * 64 + n];
        float h01 = h0s[a1 * 64 + n];
        t0s[a0 * 64 + n] = h00 * (1.f - h00) * (s0a + s0b);
        t0s[a1 * 64 + n] = h01 * (1.f - h01) * (s1a + s1b);
        if (n == 0) {
            Ei_buf[base + a0] = ePart[a0 * 2] + ePart[a0 * 2 + 1];
            Ei_buf[base + a1] = ePart[a1 * 2] + ePart[a1 * 2 + 1];
        }
    }
    __syncthreads();

    // ---- phase 4: g[f] = sum_k t0[k] * W0[k][f]  (f = n, n+64; 2 atoms) ----
    {
        const int f0 = n, f1 = n + 64;
        const float4* Pa = (const float4*)(t0s + a0 * 64);
        const float4* Pb = (const float4*)(t0s + a1 * 64);
        float g00 = 0.f, g01 = 0.f, g10 = 0.f, g11 = 0.f;
#pragma unroll
        for (int k4 = 0; k4 < H1 / 4; k4++) {
            float4 ta = Pa[k4];
            float4 tb = Pb[k4];
            const int k = k4 * 4;
#pragma unroll
            for (int u = 0; u < 4; u++) {
                float w0 = W0T[f0 * 65 + k + u];
                float w1 = W0T[f1 * 65 + k + u];
                float va = (u == 0) ? ta.x : (u == 1) ? ta.y : (u == 2) ? ta.z : ta.w;
                float vb = (u == 0) ? tb.x : (u == 1) ? tb.y : (u == 2) ? tb.z : tb.w;
                g00 = fmaf(va, w0, g00);
                g01 = fmaf(va, w1, g01);
                g10 = fmaf(vb, w0, g10);
                g11 = fmaf(vb, w1, g11);
            }
        }
        float* go0 = g_buf + (size_t)(base + a0) * Ff;
        float* go1 = g_buf + (size_t)(base + a1) * Ff;
        go0[f0] = g00; go0[f1] = g01;
        go1[f0] = g10; go1[f1] = g11;
    }
}

// ---------------------------------------------------------------------------
// Kernel 2: force, split into 2 half-blocks per atom (m 0..31 / 32..63).
// 192 threads, 16 KB smem -> ~2x resident blocks, interleaving L2 gather
// phases with the DRAM stream across blocks. Gather via cp.async (pad rows
// -> zero row); 4-deep dfeat prefetch before the gather barrier. Partials
// combined by 2-way atomicAdd (exactly 2 addends -> order-independent).
// ---------------------------------------------------------------------------
__global__ __launch_bounds__(FBLK) void force_kernel(
    const int*   __restrict__ neighbor,   // [B*N, M]
    const float* __restrict__ dfeat,      // [B*N, M, F, 3]
    float*       __restrict__ out_force)  // [B*N, 3]  (pre-zeroed)
{
    const int blk  = blockIdx.x;            // 0..8191
    const int atom = blk >> 1;
    const int half = blk & 1;
    const int b    = atom >> 11;             // N = 2048
    const int t    = threadIdx.x;

    __shared__ float sg[32 * Ff];             // 16 KB: this half's gathered rows
    __shared__ float wsum[6][3];

    // ---- gather 32 masked g rows via cp.async ----
    {
        float4*       sg4 = (float4*)sg;
        const float4* g4  = (const float4*)g_buf;
        const float4* z4  = (const float4*)g_zero;
        const int*    nb  = neighbor + atom * Mm + half * 32;
        for (int i = t; i < 32 * (Ff / 4); i += FBLK) {
            int m  = i >> 5;                 // 32 float4 per row
            int f4 = i & 31;
            int nei = __ldg(nb + m);
            const float4* src = (nei > 0)
                ? g4 + ((size_t)(b * Nn + nei - 1)) * (Ff / 4) + f4
                : z4 + f4;
            cp_async16(sg4 + i, src);
        }
        asm volatile("cp.async.commit_group;");
    }

    // ---- prefetch first 4 dfeat vectors while the gather drains ----
    const float4* dp = (const float4*)dfeat
                     + (size_t)atom * (Mm * Ff * 3 / 4) + half * 3072 + t;
    float4 v0 = __ldg(dp);
    float4 v1 = __ldg(dp + 192);
    float4 v2 = __ldg(dp + 2 * 192);
    float4 v3 = __ldg(dp + 3 * 192);

    asm volatile("cp.async.wait_group 0;" ::: "memory");
    __syncthreads();

    const int r4  = t % 96;                  // loop-invariant per thread
    const int m0  = t / 96;                  // 0..1
    const int cse = r4 % 3;
    const int f0  = (4 * r4) / 3;            // 0..126

    // A_k accumulates component c = (cse + k) % 3
    float A0 = 0.f, A1 = 0.f, A2 = 0.f;
#pragma unroll
    for (int it = 0; it < 16; it++) {
        const int m = m0 + 2 * it;           // local row 0..31
        float4 v = (it == 0) ? v0 : (it == 1) ? v1 : (it == 2) ? v2 : (it == 3) ? v3
                 : __ldg(dp + (size_t)it * 192);
        float s0 = sg[m * Ff + f0];
        float s1 = sg[m * Ff + f0 + 1];
        float sy = (cse == 2) ? s1 : s0;
        float sz = (cse == 0) ? s0 : s1;
        A0 = fmaf(v.x, s0, A0);
        A1 = fmaf(v.y, sy, A1);
        A2 = fmaf(v.z, sz, A2);
        A0 = fmaf(v.w, s1, A0);
    }
    // rotate (A0,A1,A2) -> (c0,c1,c2)
    float c0 = (cse == 0) ? A0 : (cse == 1) ? A2 : A1;
    float c1 = (cse == 0) ? A1 : (cse == 1) ? A0 : A2;
    float c2 = (cse == 0) ? A2 : (cse == 1) ? A1 : A0;

#pragma unroll
    for (int off = 16; off > 0; off >>= 1) {
        c0 += __shfl_down_sync(0xffffffffu, c0, off);
        c1 += __shfl_down_sync(0xffffffffu, c1, off);
        c2 += __shfl_down_sync(0xffffffffu, c2, off);
    }
    const int w = t >> 5;                    // 0..5
    if ((t & 31) == 0) { wsum[w][0] = c0; wsum[w][1] = c1; wsum[w][2] = c2; }
    __syncthreads();

    if (t < 3) {
        float s = 0.f;
#pragma unroll
        for (int w2 = 0; w2 < 6; w2++) s += wsum[w2][t];
        atomicAdd(out_force + atom * 3 + t, s * 1e10f);
    }
}

// ---------------------------------------------------------------------------
// Kernel 3: deterministic Etot = sum_n Ei  (double accumulation)
// ---------------------------------------------------------------------------
__global__ __launch_bounds__(256) void etot_kernel(float* __restrict__ out)
{
    const int b = blockIdx.x;
    const int t = threadIdx.x;
    __shared__ double sd[256];

    double s = 0.0;
    for (int n = t; n < Nn; n += 256) s += (double)Ei_buf[b * Nn + n];
    sd[t] = s;
    __syncthreads();
#pragma unroll
    for (int k = 128; k > 0; k >>= 1) {
        if (t < k) sd[t] += sd[t + k];
        __syncthreads();
    }
    if (t == 0) out[b] = (float)sd[0];
}

// ---------------------------------------------------------------------------
// Launch. Inputs: image, dfeat, neighbor, Egroup_weight, divider, W0, W1, Wout.
// Output: [Etot (2 floats), force (B*N*3 = 12288 floats)] flattened.
// ---------------------------------------------------------------------------
extern "C" void kernel_launch(void* const* d_in, const int* in_sizes, int n_in,
                              void* d_out, int out_size)
{
    const float* image    = (const float*)d_in[0];
    const float* dfeat    = (const float*)d_in[1];
    const int*   neighbor = (const int*)  d_in[2];
    const float* W0       = (const float*)d_in[5];
    const float* W1       = (const float*)d_in[6];
    const float* Wout     = (const float*)d_in[7];
    float* out = (float*)d_out;

    const int smem_bytes =
        (Ff * 65 + H1 * 65 + 64 + TILE * Ff + 3 * TILE * 64 + 2 * TILE) * (int)sizeof(float);
    cudaFuncSetAttribute(mlp_kernel, cudaFuncAttributeMaxDynamicSharedMemorySize, smem_bytes);

    cudaMemsetAsync(out + 2, 0, (size_t)Bb * Nn * 3 * sizeof(float));
    mlp_kernel<<<(Bb * Nn) / TILE, MLP_THREADS, smem_bytes>>>(image, W0, W1, Wout);
    force_kernel<<<Bb * Nn * 2, FBLK>>>(neighbor, dfeat, out + 2);
    etot_kernel<<<Bb, 256>>>(out);
}